// round 8
// baseline (speedup 1.0000x reference)
#include <cuda_runtime.h>
#include <cuda_bf16.h>

#define BB 4
#define TP 2048
#define TE 16384
#define DD 64
#define NBKT 1024
#define CAP 128
#define FINF 3.402823466e38f

// Scratch (allocation-free rule -> __device__ globals; zero-init at load).
__device__ float g_bkey[BB][TP];           // prices, bucket-grouped
__device__ int   g_bidx[BB][TP];           // original price indices
__device__ int   g_bstart[BB][NBKT + 1];   // price-bucket CSR offsets
__device__ int   g_bar_cnt[BB * TP];       // events-per-bar count (builder zeroes)
__device__ int   g_ev_list[BB * TP][CAP];  // event ids per bar (slot-claimed)
// Monotone synchronization state (never reset; epoch derived per launch):
__device__ unsigned int g_start;           // +1 per block per launch
__device__ int   g_ready[BB];              // builder -> call+1
__device__ int   g_done[BB];               // event blocks -> 64 per call

__device__ __forceinline__ int warp_incl_scan(int v, int lane) {
    #pragma unroll
    for (int off = 1; off < 32; off <<= 1) {
        int u = __shfl_up_sync(0xffffffffu, v, off);
        if (lane >= off) v += u;
    }
    return v;
}

// ---------------------------------------------------------------------------
// Single fused persistent kernel. Grid (64, BB) x 256 threads (256 blocks,
// all resident in one wave -> in-kernel spin-waits are safe).
// ---------------------------------------------------------------------------
__global__ __launch_bounds__(256) void ta_fused(
    const float* __restrict__ price_ts,
    const float* __restrict__ event_ts,
    const float* __restrict__ event_vals,
    float* __restrict__ out, int has_cov)
{
    __shared__ float sk[TP];
    __shared__ int   si[TP];
    __shared__ int   sbs[NBKT + 1];
    __shared__ int   cnt[NBKT];        // builder scratch
    __shared__ int   wsum[8];
    __shared__ int   s_call;

    const int t = threadIdx.x;
    const int lane = t & 31, wid = t >> 5;
    const int x = blockIdx.x;          // 0..63
    const int b = blockIdx.y;          // 0..BB-1

    // ---- epoch: identical for all 256 blocks of this launch ----
    if (t == 0) {
        unsigned int old = atomicAdd(&g_start, 1u);
        s_call = (int)(old >> 8);      // 256 blocks per call
    }
    __syncthreads();
    const int call = s_call;

    // ---- prefetch my event timestamp (overlaps builder latency) ----
    const int e = x * 256 + t;
    const float et = event_ts[b * TE + e];

    if (x == 0) {
        // ================= builder: bucket this batch's prices =============
        #pragma unroll
        for (int i = t; i < TP; i += 256) g_bar_cnt[b * TP + i] = 0;
        #pragma unroll
        for (int i = t; i < NBKT; i += 256) cnt[i] = 0;

        float pv[8]; int kb[8];
        #pragma unroll
        for (int j = 0; j < 8; ++j) {
            pv[j] = price_ts[b * TP + t + 256 * j];
            kb[j] = min((int)(pv[j] * (float)NBKT), NBKT - 1);
        }
        __syncthreads();
        #pragma unroll
        for (int j = 0; j < 8; ++j) atomicAdd(&cnt[kb[j]], 1);
        __syncthreads();

        // scan 1024 counts with 256 threads (4 per thread)
        const int c0 = cnt[4 * t], c1 = cnt[4 * t + 1];
        const int c2 = cnt[4 * t + 2], c3 = cnt[4 * t + 3];
        const int ts = c0 + c1 + c2 + c3;
        int incl = warp_incl_scan(ts, lane);
        if (lane == 31) wsum[wid] = incl;
        __syncthreads();
        if (t == 0) {
            int acc = 0;
            #pragma unroll
            for (int w = 0; w < 8; ++w) { int v = wsum[w]; wsum[w] = acc; acc += v; }
        }
        __syncthreads();
        const int base = wsum[wid] + (incl - ts);    // exclusive
        sbs[4 * t]     = base;
        sbs[4 * t + 1] = base + c0;
        sbs[4 * t + 2] = base + c0 + c1;
        sbs[4 * t + 3] = base + c0 + c1 + c2;
        if (t == 0) sbs[NBKT] = TP;
        #pragma unroll
        for (int i = t; i < NBKT; i += 256) cnt[i] = 0;   // reuse as cursors
        __syncthreads();

        #pragma unroll
        for (int j = 0; j < 8; ++j) {
            const int pos = sbs[kb[j]] + atomicAdd(&cnt[kb[j]], 1);
            sk[pos] = pv[j];
            si[pos] = t + 256 * j;
        }
        __syncthreads();

        // publish to global for the other 63 blocks of this batch
        #pragma unroll
        for (int i = t; i < TP; i += 256) {
            g_bkey[b][i] = sk[i];
            g_bidx[b][i] = si[i];
        }
        #pragma unroll
        for (int i = t; i <= NBKT; i += 256) g_bstart[b][i] = sbs[i];
        __threadfence();
        __syncthreads();
        if (t == 0) atomicExch(&g_ready[b], call + 1);
    } else {
        // ================= waiter: spin for builder, then load =============
        if (t == 0) {
            volatile int* vr = &g_ready[b];
            while (*vr < call + 1) __nanosleep(64);
        }
        __syncthreads();
        __threadfence();
        for (int i = t; i < TP; i += 256) {
            sk[i] = g_bkey[b][i];
            si[i] = g_bidx[b][i];
        }
        for (int i = t; i <= NBKT; i += 256) sbs[i] = g_bstart[b][i];
        __syncthreads();
    }

    // ================= event phase: exact argmin + slot claim =============
    {
        const int bkt = min(max((int)(et * (float)NBKT), 0), NBKT - 1);
        float best = FINF;
        int   bi   = 0x7fffffff;

        const int j0 = sbs[max(bkt - 1, 0)];
        const int j1 = sbs[min(bkt + 1, NBKT - 1) + 1];
        for (int j = j0; j < j1; ++j) {
            const float d = fabsf(et - sk[j]);
            const int   ix = si[j];
            if (d < best || (d == best && ix < bi)) { best = d; bi = ix; }
        }
        int r = 1;
        while (true) {
            const int lb = bkt - r - 1, rb = bkt + r + 1;
            const bool lv = (lb >= 0), rv = (rb <= NBKT - 1);
            const float lB = lv ? (et - (float)(bkt - r) / (float)NBKT) : FINF;
            const float rB = rv ? ((float)rb / (float)NBKT - et) : FINF;
            const bool needL = lv && !(best < lB);
            const bool needR = rv && !(best < rB);
            if (!needL && !needR) break;
            if (needL)
                for (int j = sbs[lb]; j < sbs[lb + 1]; ++j) {
                    const float d = fabsf(et - sk[j]);
                    const int ix = si[j];
                    if (d < best || (d == best && ix < bi)) { best = d; bi = ix; }
                }
            if (needR)
                for (int j = sbs[rb]; j < sbs[rb + 1]; ++j) {
                    const float d = fabsf(et - sk[j]);
                    const int ix = si[j];
                    if (d < best || (d == best && ix < bi)) { best = d; bi = ix; }
                }
            ++r;
        }

        const int slot = atomicAdd(&g_bar_cnt[b * TP + bi], 1);
        if (slot < CAP) g_ev_list[b * TP + bi][slot] = e;
    }
    __threadfence();
    __syncthreads();
    if (t == 0) atomicAdd(&g_done[b], 1);

    // ================= gather phase: 32 bars per block ====================
    if (t == 0) {
        volatile int* vd = &g_done[b];
        const int target = 64 * (call + 1);
        while (*vd < target) __nanosleep(64);
    }
    __syncthreads();
    __threadfence();

    const int grp = t >> 6;            // 0..3
    const int d   = t & 63;
    const float* basep = event_vals + (size_t)b * TE * DD + d;

    #pragma unroll
    for (int it = 0; it < 8; ++it) {
        const int bar = x * 32 + it * 4 + grp;
        const int row = b * TP + bar;

        const int n = g_bar_cnt[row];
        const int m = min(n, CAP);
        const int* lst = g_ev_list[row];

        float s0 = 0.f, s1 = 0.f, s2 = 0.f, s3 = 0.f;
        int j = 0;
        for (; j + 3 < m; j += 4) {
            const int e0 = __ldg(&lst[j]);
            const int e1 = __ldg(&lst[j + 1]);
            const int e2 = __ldg(&lst[j + 2]);
            const int e3 = __ldg(&lst[j + 3]);
            s0 += __ldg(basep + (size_t)e0 * DD);
            s1 += __ldg(basep + (size_t)e1 * DD);
            s2 += __ldg(basep + (size_t)e2 * DD);
            s3 += __ldg(basep + (size_t)e3 * DD);
        }
        for (; j < m; ++j) {
            const int e0 = __ldg(&lst[j]);
            s0 += __ldg(basep + (size_t)e0 * DD);
        }
        const float sum = (s0 + s1) + (s2 + s3);
        out[(size_t)row * DD + d] = (n > 0) ? (sum / (float)n) : 0.0f;
        if (has_cov && d == 0)
            out[(size_t)BB * TP * DD + row] = (n > 0) ? 1.0f : 0.0f;
    }
}

// ---------------------------------------------------------------------------
extern "C" void kernel_launch(void* const* d_in, const int* in_sizes, int n_in,
                              void* d_out, int out_size) {
    const float* price_ts   = (const float*)d_in[0];
    const float* event_ts   = (const float*)d_in[1];
    const float* event_vals = (const float*)d_in[2];
    float* out = (float*)d_out;

    const int has_cov = (out_size >= BB * TP * DD + BB * TP) ? 1 : 0;

    dim3 grid(64, BB);
    ta_fused<<<grid, 256>>>(price_ts, event_ts, event_vals, out, has_cov);
}

// round 10
// speedup vs baseline: 1.7860x; 1.7860x over previous
#include <cuda_runtime.h>
#include <cuda_bf16.h>

#define BB 4
#define TP 2048
#define TE 16384
#define DD 64
#define NBKT 1024
#define CAP 128
#define FINF 3.402823466e38f

// Scratch (allocation-free rule -> __device__ globals; zero-init at load).
// g_bar_cnt invariant: zero at kernel_launch entry (gather resets after a
// block-wide barrier that orders all reads before the reset).
__device__ int g_bar_cnt[BB * TP];
__device__ int g_ev_list[BB * TP][CAP];

__device__ __forceinline__ int warp_incl_scan(int v, int lane) {
    #pragma unroll
    for (int off = 1; off < 32; off <<= 1) {
        int u = __shfl_up_sync(0xffffffffu, v, off);
        if (lane >= off) v += u;
    }
    return v;
}

// ---------------------------------------------------------------------------
// K1: each block independently builds the price-bucket structure in its own
// smem (no cross-block sync), then runs the exact argmin for its 256 events
// and claims slots. Grid (64, BB) x 256.
// ---------------------------------------------------------------------------
__global__ __launch_bounds__(256) void k_align(
    const float* __restrict__ price_ts,
    const float* __restrict__ event_ts)
{
    __shared__ float sk[TP];
    __shared__ int   si[TP];
    __shared__ int   sbs[NBKT + 1];
    __shared__ int   cnt[NBKT];
    __shared__ int   wsum[8];

    const int t = threadIdx.x;
    const int lane = t & 31, wid = t >> 5;
    const int x = blockIdx.x;          // 0..63
    const int b = blockIdx.y;          // 0..BB-1

    // prefetch my event timestamp (overlaps the build)
    const int e = x * 256 + t;
    const float et = event_ts[b * TE + e];

    // ---- build bucket structure in-block (DRAM once, L2 after) ----
    #pragma unroll
    for (int i = t; i < NBKT; i += 256) cnt[i] = 0;

    float pv[8]; int kb[8];
    #pragma unroll
    for (int j = 0; j < 8; ++j) {
        pv[j] = price_ts[b * TP + t + 256 * j];
        kb[j] = min((int)(pv[j] * (float)NBKT), NBKT - 1);
    }
    __syncthreads();
    #pragma unroll
    for (int j = 0; j < 8; ++j) atomicAdd(&cnt[kb[j]], 1);
    __syncthreads();

    // exclusive scan of 1024 counts with 256 threads (4/thread)
    const int c0 = cnt[4 * t], c1 = cnt[4 * t + 1];
    const int c2 = cnt[4 * t + 2], c3 = cnt[4 * t + 3];
    const int ts = c0 + c1 + c2 + c3;
    int incl = warp_incl_scan(ts, lane);
    if (lane == 31) wsum[wid] = incl;
    __syncthreads();
    if (t == 0) {
        int acc = 0;
        #pragma unroll
        for (int w = 0; w < 8; ++w) { int v = wsum[w]; wsum[w] = acc; acc += v; }
    }
    __syncthreads();
    const int base = wsum[wid] + (incl - ts);
    sbs[4 * t]     = base;
    sbs[4 * t + 1] = base + c0;
    sbs[4 * t + 2] = base + c0 + c1;
    sbs[4 * t + 3] = base + c0 + c1 + c2;
    if (t == 0) sbs[NBKT] = TP;
    #pragma unroll
    for (int i = t; i < NBKT; i += 256) cnt[i] = 0;   // reuse as cursors
    __syncthreads();

    #pragma unroll
    for (int j = 0; j < 8; ++j) {
        const int pos = sbs[kb[j]] + atomicAdd(&cnt[kb[j]], 1);
        sk[pos] = pv[j];
        si[pos] = t + 256 * j;
    }
    __syncthreads();

    // ---- exact argmin (lexicographic (fabsf-dist, orig-idx) min; R4) ----
    const int bkt = min(max((int)(et * (float)NBKT), 0), NBKT - 1);
    float best = FINF;
    int   bi   = 0x7fffffff;

    {
        const int j0 = sbs[max(bkt - 1, 0)];
        const int j1 = sbs[min(bkt + 1, NBKT - 1) + 1];
        for (int j = j0; j < j1; ++j) {
            const float d = fabsf(et - sk[j]);
            const int   ix = si[j];
            if (d < best || (d == best && ix < bi)) { best = d; bi = ix; }
        }
    }
    int r = 1;
    while (true) {
        const int lb = bkt - r - 1, rb = bkt + r + 1;
        const bool lv = (lb >= 0), rv = (rb <= NBKT - 1);
        const float lB = lv ? (et - (float)(bkt - r) / (float)NBKT) : FINF;
        const float rB = rv ? ((float)rb / (float)NBKT - et) : FINF;
        const bool needL = lv && !(best < lB);
        const bool needR = rv && !(best < rB);
        if (!needL && !needR) break;
        if (needL)
            for (int j = sbs[lb]; j < sbs[lb + 1]; ++j) {
                const float d = fabsf(et - sk[j]);
                const int ix = si[j];
                if (d < best || (d == best && ix < bi)) { best = d; bi = ix; }
            }
        if (needR)
            for (int j = sbs[rb]; j < sbs[rb + 1]; ++j) {
                const float d = fabsf(et - sk[j]);
                const int ix = si[j];
                if (d < best || (d == best && ix < bi)) { best = d; bi = ix; }
            }
        ++r;
    }

    const int slot = atomicAdd(&g_bar_cnt[b * TP + bi], 1);
    if (slot < CAP) g_ev_list[b * TP + bi][slot] = e;
}

// ---------------------------------------------------------------------------
// K2: gather + mean + coverage straight to d_out. ALL threads read their
// row's count FIRST, then a block-wide barrier, THEN lane 0 resets it
// (restores the zero invariant for the next graph replay race-free).
// ---------------------------------------------------------------------------
__global__ __launch_bounds__(256) void k_gather(
    const float* __restrict__ event_vals,
    float* __restrict__ out, int has_cov)
{
    const int grp = threadIdx.x >> 6;           // 0..3
    const int d   = threadIdx.x & 63;
    const int row = blockIdx.x * 4 + grp;       // 0 .. B*TP-1
    const int b   = row >> 11;

    const int n = g_bar_cnt[row];               // every thread reads first
    __syncthreads();                            // all reads ordered before...
    if (d == 0) g_bar_cnt[row] = 0;             // ...the reset (race-free)

    const int m = min(n, CAP);
    const int* lst = g_ev_list[row];

    const float* base = event_vals + (size_t)b * TE * DD + d;

    float s0 = 0.f, s1 = 0.f, s2 = 0.f, s3 = 0.f;
    int j = 0;
    for (; j + 3 < m; j += 4) {
        const int e0 = __ldg(&lst[j]);
        const int e1 = __ldg(&lst[j + 1]);
        const int e2 = __ldg(&lst[j + 2]);
        const int e3 = __ldg(&lst[j + 3]);
        s0 += __ldg(base + (size_t)e0 * DD);
        s1 += __ldg(base + (size_t)e1 * DD);
        s2 += __ldg(base + (size_t)e2 * DD);
        s3 += __ldg(base + (size_t)e3 * DD);
    }
    for (; j < m; ++j) {
        const int e0 = __ldg(&lst[j]);
        s0 += __ldg(base + (size_t)e0 * DD);
    }

    const float sum = (s0 + s1) + (s2 + s3);
    out[(size_t)row * DD + d] = (n > 0) ? (sum / (float)n) : 0.0f;

    if (has_cov && d == 0)
        out[(size_t)BB * TP * DD + row] = (n > 0) ? 1.0f : 0.0f;
}

// ---------------------------------------------------------------------------
extern "C" void kernel_launch(void* const* d_in, const int* in_sizes, int n_in,
                              void* d_out, int out_size) {
    const float* price_ts   = (const float*)d_in[0];
    const float* event_ts   = (const float*)d_in[1];
    const float* event_vals = (const float*)d_in[2];
    float* out = (float*)d_out;

    const int has_cov = (out_size >= BB * TP * DD + BB * TP) ? 1 : 0;

    dim3 agrid(64, BB);
    k_align<<<agrid, 256>>>(price_ts, event_ts);

    k_gather<<<BB * TP / 4, 256>>>(event_vals, out, has_cov);
}